// round 8
// baseline (speedup 1.0000x reference)
#include <cuda_runtime.h>
#include <cuda_bf16.h>
#include <cstdint>

#define BATCH 512
#define FEAT  512
#define NBLK  128

#define AS_STR 520                       // 512 + 8 bf16 pad
#define AS_BYTES (64 * AS_STR * 2)       // 66560
#define BS_BYTES (32 * AS_STR * 2)       // 33280
#define SMEM_TOTAL (AS_BYTES + BS_BYTES) // 99840

__device__ float g_refs[BATCH * 8];                 // refs[r][j] = S[r, 8*(r/8)+j]
__device__ unsigned long long g_rk[BATCH * 8];      // fixed-point rk partial sums
__device__ unsigned g_ctr = 0;
__device__ volatile unsigned g_epoch = 0;
__device__ unsigned long long g_sum = 0;
__device__ unsigned g_done = 0;

#define RK_SCALE 65536.0f
#define INV_RK   (1.0f / 65536.0f)
#define SUM_SCALE 1073741824.0f          // 2^30
#define INV_SUM  (1.0 / 1073741824.0)

__device__ __forceinline__ void grid_barrier(int tid, unsigned target) {
    __syncthreads();
    if (tid == 0) {
        __threadfence();
        const unsigned prev = atomicAdd(&g_ctr, 1);
        if (prev == NBLK - 1) {
            g_ctr = 0;
            __threadfence();
            g_epoch = target;
        } else {
            while ((int)(g_epoch - target) < 0) {}
        }
        __threadfence();
    }
    __syncthreads();
}

__global__ void __launch_bounds__(256, 1) fused_kernel(const float* __restrict__ fs,
                                                       const float* __restrict__ ft,
                                                       float* __restrict__ out) {
    extern __shared__ __align__(16) char smem[];
    __nv_bfloat16 (*As)[AS_STR] = (__nv_bfloat16(*)[AS_STR])smem;
    __nv_bfloat16 (*Bs)[AS_STR] = (__nv_bfloat16(*)[AS_STR])(smem + AS_BYTES);

    __shared__ float smrk[8][8][16];   // [warp][g][row0:8j | row1:8j]
    __shared__ unsigned ep0_sm;

    const int tid   = threadIdx.x;
    const int bid   = blockIdx.y * 16 + blockIdx.x;
    const int mTile = blockIdx.y * 64;
    const int nTile = blockIdx.x * 32;
    const int warp  = tid >> 5;
    const int lane  = tid & 31;
    const int wm    = warp & 3;
    const int wn    = warp >> 2;

    if (tid == 0) ep0_sm = g_epoch;
    // zero this block's rows of g_rk (rows bid*4 .. bid*4+3)
    if (tid < 32) g_rk[bid * 32 + tid] = 0ull;

    // ================= Stage A and B tiles (fp32 -> bf16) ====================
    {
        const float4* ag = (const float4*)(fs + mTile * FEAT);
        #pragma unroll 16
        for (int v = 0; v < 32; v++) {
            const int idx = tid + v * 256;
            const int row = idx >> 7, c4 = idx & 127;
            const float4 x = ag[row * 128 + c4];
            __nv_bfloat162 h0 = __floats2bfloat162_rn(x.x, x.y);
            __nv_bfloat162 h1 = __floats2bfloat162_rn(x.z, x.w);
            uint2 pk = make_uint2(*(uint32_t*)&h0, *(uint32_t*)&h1);
            *(uint2*)&As[row][c4 * 4] = pk;
        }
        const float4* bg = (const float4*)(ft + nTile * FEAT);
        #pragma unroll 16
        for (int v = 0; v < 16; v++) {
            const int idx = tid + v * 256;
            const int row = idx >> 7, c4 = idx & 127;
            const float4 x = bg[row * 128 + c4];
            __nv_bfloat162 h0 = __floats2bfloat162_rn(x.x, x.y);
            __nv_bfloat162 h1 = __floats2bfloat162_rn(x.z, x.w);
            uint2 pk = make_uint2(*(uint32_t*)&h0, *(uint32_t*)&h1);
            *(uint2*)&Bs[row][c4 * 4] = pk;
        }
    }
    __syncthreads();

    // ================= Mainloop: 32 k-steps, no syncs ========================
    float acc[2][4] = {};
    const int a_row = 16 * wm + (lane & 7) + ((lane >> 3) & 1) * 8;
    const int a_k8  = (lane >> 4) * 8;
    const int b_row = 16 * wn + (lane & 7) + (lane >> 4) * 8;
    const int b_k8  = ((lane >> 3) & 1) * 8;

    const uint32_t abase = (uint32_t)__cvta_generic_to_shared(&As[a_row][a_k8]);
    const uint32_t bbase = (uint32_t)__cvta_generic_to_shared(&Bs[b_row][b_k8]);

    #pragma unroll
    for (int kk = 0; kk < 32; kk++) {
        const uint32_t koff = kk * 32;   // bytes
        uint32_t a0, a1, a2, a3, b0, b1, b2, b3;
        asm volatile("ldmatrix.sync.aligned.m8n8.x4.shared.b16 {%0,%1,%2,%3}, [%4];\n"
                     : "=r"(a0), "=r"(a1), "=r"(a2), "=r"(a3) : "r"(abase + koff));
        asm volatile("ldmatrix.sync.aligned.m8n8.x4.shared.b16 {%0,%1,%2,%3}, [%4];\n"
                     : "=r"(b0), "=r"(b1), "=r"(b2), "=r"(b3) : "r"(bbase + koff));
        asm volatile("mma.sync.aligned.m16n8k16.row.col.f32.bf16.bf16.f32 "
                     "{%0,%1,%2,%3}, {%4,%5,%6,%7}, {%8,%9}, {%0,%1,%2,%3};\n"
                     : "+f"(acc[0][0]), "+f"(acc[0][1]), "+f"(acc[0][2]), "+f"(acc[0][3])
                     : "r"(a0), "r"(a1), "r"(a2), "r"(a3), "r"(b0), "r"(b1));
        asm volatile("mma.sync.aligned.m16n8k16.row.col.f32.bf16.bf16.f32 "
                     "{%0,%1,%2,%3}, {%4,%5,%6,%7}, {%8,%9}, {%0,%1,%2,%3};\n"
                     : "+f"(acc[1][0]), "+f"(acc[1][1]), "+f"(acc[1][2]), "+f"(acc[1][3])
                     : "r"(a0), "r"(a1), "r"(a2), "r"(a3), "r"(b2), "r"(b3));
    }

    // Thread's S coordinates: rows r0, r0+8; cols cb + 8h + e
    const int g  = lane >> 2, t = lane & 3;
    const int r0 = mTile + 16 * wm + g;
    const int r1 = r0 + 8;
    const int cb = nTile + 16 * wn + t * 2;

    // ================= Publish refs (diagonal CTAs hit the condition) =======
    #pragma unroll
    for (int h = 0; h < 2; h++) {
        #pragma unroll
        for (int e = 0; e < 2; e++) {
            const int c = cb + 8 * h + e;
            if ((c >> 3) == (r0 >> 3)) g_refs[r0 * 8 + (c & 7)] = acc[h][e];
            if ((c >> 3) == (r1 >> 3)) g_refs[r1 * 8 + (c & 7)] = acc[h][2 + e];
        }
    }

    grid_barrier(tid, ep0_sm + 1);

    // ================= Partial rk from registers =============================
    float rf0[8], rf1[8];
    *(float4*)&rf0[0] = __ldcg((const float4*)&g_refs[r0 * 8]);
    *(float4*)&rf0[4] = __ldcg((const float4*)&g_refs[r0 * 8 + 4]);
    *(float4*)&rf1[0] = __ldcg((const float4*)&g_refs[r1 * 8]);
    *(float4*)&rf1[4] = __ldcg((const float4*)&g_refs[r1 * 8 + 4]);

    float p0[8] = {}, p1[8] = {};
    #pragma unroll
    for (int h = 0; h < 2; h++) {
        #pragma unroll
        for (int e = 0; e < 2; e++) {
            const float v0 = acc[h][e];
            const float v1 = acc[h][2 + e];
            #pragma unroll
            for (int j = 0; j < 8; j++) {
                p0[j] += fmaxf(v0 - rf0[j], 0.f);
                p1[j] += fmaxf(v1 - rf1[j], 0.f);
            }
        }
    }
    // reduce over the 4 lanes (t) sharing each row
    #pragma unroll
    for (int o = 1; o <= 2; o <<= 1) {
        #pragma unroll
        for (int j = 0; j < 8; j++) {
            p0[j] += __shfl_down_sync(0xffffffffu, p0[j], o);
            p1[j] += __shfl_down_sync(0xffffffffu, p1[j], o);
        }
    }
    if (t == 0) {
        #pragma unroll
        for (int j = 0; j < 8; j++) { smrk[warp][g][j] = p0[j]; smrk[warp][g][8 + j] = p1[j]; }
    }
    __syncthreads();

    // combine wn halves + fixed-point atomic into g_rk: 512 entries, 2/thread
    {
        #pragma unroll
        for (int u = 0; u < 2; u++) {
            const int idx = tid * 2 + u;           // 0..511
            const int ewm = idx >> 7;              // 0..3
            const int eg  = (idx >> 4) & 7;        // 0..7
            const int ek  = idx & 15;              // 0..15
            const float val = smrk[ewm][eg][ek] + smrk[ewm + 4][eg][ek];
            const int row = mTile + 16 * ewm + eg + ((ek >> 3) ? 8 : 0);
            const int j   = ek & 7;
            atomicAdd(&g_rk[row * 8 + j],
                      (unsigned long long)llrintf(val * RK_SCALE));
        }
    }

    grid_barrier(tid, ep0_sm + 2);

    // ================= Phase 3: ratios for rows bid*4 .. bid*4+3 =============
    float ratio = 0.f;
    if (tid < 32) {
        const int rl = tid >> 3, j = tid & 7;
        const int r  = bid * 4 + rl;
        float rfs[8];
        *(float4*)&rfs[0] = __ldcg((const float4*)&g_refs[r * 8]);
        *(float4*)&rfs[4] = __ldcg((const float4*)&g_refs[r * 8 + 4]);
        const unsigned long long rkq = __ldcg(&g_rk[r * 8 + j]);
        const float rk = 1.f + (float)rkq * INV_RK;
        const float pj = rfs[j];
        float ps = 0.f;
        #pragma unroll
        for (int k = 0; k < 8; k++) ps += fmaxf(rfs[k] - pj, 0.f);
        ratio = (1.f + ps) / rk;
        #pragma unroll
        for (int o = 16; o > 0; o >>= 1)
            ratio += __shfl_down_sync(0xffffffffu, ratio, o);
    }

    if (tid == 0) {
        atomicAdd(&g_sum, (unsigned long long)llrintf(ratio * SUM_SCALE));
        __threadfence();
        const unsigned prev = atomicAdd(&g_done, 1);
        if (prev == NBLK - 1) {
            const unsigned long long tot = *((volatile unsigned long long*)&g_sum);
            out[0] = (float)(1.0 - ((double)tot * INV_SUM) * (1.0 / 4096.0));
            g_sum  = 0;
            g_done = 0;
        }
    }
}

extern "C" void kernel_launch(void* const* d_in, const int* in_sizes, int n_in,
                              void* d_out, int out_size) {
    const float* fs = (const float*)d_in[0];
    const float* ft = (const float*)d_in[1];
    float* out = (float*)d_out;

    cudaFuncSetAttribute(fused_kernel,
                         cudaFuncAttributeMaxDynamicSharedMemorySize, SMEM_TOTAL);
    fused_kernel<<<dim3(16, 8), 256, SMEM_TOTAL>>>(fs, ft, out);
}

// round 9
// speedup vs baseline: 1.1400x; 1.1400x over previous
#include <cuda_runtime.h>
#include <cuda_bf16.h>
#include <cstdint>

#define BATCH 512
#define FEAT  512
#define NBLK  128
#define NTHR  512

#define AS_STR 520                         // 512 + 8 bf16 pad
#define AS_BYTES (64 * AS_STR * 2)         // 66560
#define BS_BYTES (32 * AS_STR * 2)         // 33280
#define CS_STR 34                          // 32 + 2 pad floats
#define CS_BYTES (64 * CS_STR * 4)         // 8704
#define SMEM_TOTAL (AS_BYTES + BS_BYTES + CS_BYTES)   // 108544

__device__ float g_S[BATCH * BATCH];
__device__ unsigned g_ctr = 0;
__device__ volatile unsigned g_epoch = 0;
__device__ unsigned long long g_sum = 0;
__device__ unsigned g_done = 0;

#define SUM_SCALE 1073741824.0f            // 2^30
#define INV_SUM   (1.0 / 1073741824.0)

__global__ void __launch_bounds__(NTHR, 1) fused_kernel(const float* __restrict__ fs,
                                                        const float* __restrict__ ft,
                                                        float* __restrict__ out) {
    extern __shared__ __align__(16) char smem[];
    __nv_bfloat16 (*As)[AS_STR] = (__nv_bfloat16(*)[AS_STR])smem;
    __nv_bfloat16 (*Bs)[AS_STR] = (__nv_bfloat16(*)[AS_STR])(smem + AS_BYTES);
    float (*Cs)[CS_STR]         = (float(*)[CS_STR])(smem + AS_BYTES + BS_BYTES);

    __shared__ float refs[4][8];
    __shared__ float wr[16][8];
    __shared__ unsigned ep0_sm;

    const int tid   = threadIdx.x;
    const int bid   = blockIdx.y * 16 + blockIdx.x;
    const int mTile = blockIdx.y * 64;
    const int nTile = blockIdx.x * 32;
    const int warp  = tid >> 5;
    const int lane  = tid & 31;
    const int kh    = warp >> 3;           // k-half: 0 or 1
    const int wq    = warp & 7;
    const int wm    = wq & 3;
    const int wn    = wq >> 2;

    if (tid == 0) ep0_sm = g_epoch;

    // ================= Stage A and B tiles (fp32 -> bf16), 512 loaders =======
    {
        const float4* ag = (const float4*)(fs + mTile * FEAT);
        #pragma unroll 16
        for (int v = 0; v < 16; v++) {
            const int idx = tid + v * NTHR;
            const int row = idx >> 7, c4 = idx & 127;
            const float4 x = ag[row * 128 + c4];
            __nv_bfloat162 h0 = __floats2bfloat162_rn(x.x, x.y);
            __nv_bfloat162 h1 = __floats2bfloat162_rn(x.z, x.w);
            uint2 pk = make_uint2(*(uint32_t*)&h0, *(uint32_t*)&h1);
            *(uint2*)&As[row][c4 * 4] = pk;
        }
        const float4* bg = (const float4*)(ft + nTile * FEAT);
        #pragma unroll 8
        for (int v = 0; v < 8; v++) {
            const int idx = tid + v * NTHR;
            const int row = idx >> 7, c4 = idx & 127;
            const float4 x = bg[row * 128 + c4];
            __nv_bfloat162 h0 = __floats2bfloat162_rn(x.x, x.y);
            __nv_bfloat162 h1 = __floats2bfloat162_rn(x.z, x.w);
            uint2 pk = make_uint2(*(uint32_t*)&h0, *(uint32_t*)&h1);
            *(uint2*)&Bs[row][c4 * 4] = pk;
        }
    }
    __syncthreads();

    // ================= Mainloop: 16 k-steps per warp (k-half split) ==========
    float acc[2][4] = {};
    const int a_row = 16 * wm + (lane & 7) + ((lane >> 3) & 1) * 8;
    const int a_k8  = (lane >> 4) * 8;
    const int b_row = 16 * wn + (lane & 7) + (lane >> 4) * 8;
    const int b_k8  = ((lane >> 3) & 1) * 8;

    const uint32_t abase = (uint32_t)__cvta_generic_to_shared(&As[a_row][a_k8]) + kh * 512;
    const uint32_t bbase = (uint32_t)__cvta_generic_to_shared(&Bs[b_row][b_k8]) + kh * 512;

    #pragma unroll
    for (int kk = 0; kk < 16; kk++) {
        const uint32_t koff = kk * 32;     // bytes
        uint32_t a0, a1, a2, a3, b0, b1, b2, b3;
        asm volatile("ldmatrix.sync.aligned.m8n8.x4.shared.b16 {%0,%1,%2,%3}, [%4];\n"
                     : "=r"(a0), "=r"(a1), "=r"(a2), "=r"(a3) : "r"(abase + koff));
        asm volatile("ldmatrix.sync.aligned.m8n8.x4.shared.b16 {%0,%1,%2,%3}, [%4];\n"
                     : "=r"(b0), "=r"(b1), "=r"(b2), "=r"(b3) : "r"(bbase + koff));
        asm volatile("mma.sync.aligned.m16n8k16.row.col.f32.bf16.bf16.f32 "
                     "{%0,%1,%2,%3}, {%4,%5,%6,%7}, {%8,%9}, {%0,%1,%2,%3};\n"
                     : "+f"(acc[0][0]), "+f"(acc[0][1]), "+f"(acc[0][2]), "+f"(acc[0][3])
                     : "r"(a0), "r"(a1), "r"(a2), "r"(a3), "r"(b0), "r"(b1));
        asm volatile("mma.sync.aligned.m16n8k16.row.col.f32.bf16.bf16.f32 "
                     "{%0,%1,%2,%3}, {%4,%5,%6,%7}, {%8,%9}, {%0,%1,%2,%3};\n"
                     : "+f"(acc[1][0]), "+f"(acc[1][1]), "+f"(acc[1][2]), "+f"(acc[1][3])
                     : "r"(a0), "r"(a1), "r"(a2), "r"(a3), "r"(b2), "r"(b3));
    }

    // ================= Epilogue: combine k-halves, write S ===================
    const int g = lane >> 2, t = lane & 3;
    const int lr0 = 16 * wm + g;           // local row in [0,64)
    const int lc  = 16 * wn + t * 2;       // local col in [0,32)

    if (kh == 1) {
        #pragma unroll
        for (int h = 0; h < 2; h++) {
            *(float2*)&Cs[lr0][lc + 8 * h]     = make_float2(acc[h][0], acc[h][1]);
            *(float2*)&Cs[lr0 + 8][lc + 8 * h] = make_float2(acc[h][2], acc[h][3]);
        }
    }
    __syncthreads();
    if (kh == 0) {
        const int row0 = mTile + lr0;
        #pragma unroll
        for (int h = 0; h < 2; h++) {
            const float2 u0 = *(float2*)&Cs[lr0][lc + 8 * h];
            const float2 u1 = *(float2*)&Cs[lr0 + 8][lc + 8 * h];
            const int col = nTile + lc + 8 * h;
            *(float2*)&g_S[row0 * BATCH + col] =
                make_float2(acc[h][0] + u0.x, acc[h][1] + u0.y);
            *(float2*)&g_S[(row0 + 8) * BATCH + col] =
                make_float2(acc[h][2] + u1.x, acc[h][3] + u1.y);
        }
    }
    __syncthreads();

    // ================= Grid barrier (epoch-based) =============================
    if (tid == 0) {
        __threadfence();
        const unsigned ep0 = ep0_sm;
        const unsigned prev = atomicAdd(&g_ctr, 1);
        if (prev == NBLK - 1) {
            g_ctr = 0;
            __threadfence();
            g_epoch = ep0 + 1;
        } else {
            while (g_epoch == ep0) {}
        }
        __threadfence();
    }
    __syncthreads();

    // ================= Phase 2: 4 rows/block, 128 threads/row ================
    const int row_l = tid >> 7;            // 0..3
    const int c     = tid & 127;           // float4 chunk
    const int r     = bid * 4 + row_l;
    const float4 v = ((const float4*)(g_S + r * BATCH))[c];

    const int rc0 = (r & ~7) >> 2;
    if (c == rc0)     *(float4*)&refs[row_l][0] = v;
    if (c == rc0 + 1) *(float4*)&refs[row_l][4] = v;
    __syncthreads();

    float p[8];
    #pragma unroll
    for (int j = 0; j < 8; j++) p[j] = refs[row_l][j];

    float s8[8];
    #pragma unroll
    for (int j = 0; j < 8; j++) {
        s8[j] = fmaxf(v.x - p[j], 0.f) + fmaxf(v.y - p[j], 0.f)
              + fmaxf(v.z - p[j], 0.f) + fmaxf(v.w - p[j], 0.f);
    }
    #pragma unroll
    for (int o = 16; o > 0; o >>= 1)
        #pragma unroll
        for (int j = 0; j < 8; j++)
            s8[j] += __shfl_down_sync(0xffffffffu, s8[j], o);
    if (lane == 0) {
        #pragma unroll
        for (int j = 0; j < 8; j++) wr[warp][j] = s8[j];
    }
    __syncthreads();

    float ratio = 0.f;
    if (tid < 32) {
        const int rl = tid >> 3, j = tid & 7;
        const float rk = 1.f + wr[rl * 4][j] + wr[rl * 4 + 1][j]
                             + wr[rl * 4 + 2][j] + wr[rl * 4 + 3][j];
        const float pj = refs[rl][j];
        float ps = 0.f;
        #pragma unroll
        for (int k = 0; k < 8; k++) ps += fmaxf(refs[rl][k] - pj, 0.f);
        ratio = (1.f + ps) / rk;
        #pragma unroll
        for (int o = 16; o > 0; o >>= 1)
            ratio += __shfl_down_sync(0xffffffffu, ratio, o);
    }

    // ================= Deterministic fixed-point tail ========================
    if (tid == 0) {
        atomicAdd(&g_sum, (unsigned long long)llrintf(ratio * SUM_SCALE));
        __threadfence();
        const unsigned prev = atomicAdd(&g_done, 1);
        if (prev == NBLK - 1) {
            const unsigned long long tot = *((volatile unsigned long long*)&g_sum);
            out[0] = (float)(1.0 - ((double)tot * INV_SUM) * (1.0 / 4096.0));
            g_sum  = 0;
            g_done = 0;
        }
    }
}

extern "C" void kernel_launch(void* const* d_in, const int* in_sizes, int n_in,
                              void* d_out, int out_size) {
    const float* fs = (const float*)d_in[0];
    const float* ft = (const float*)d_in[1];
    float* out = (float*)d_out;

    cudaFuncSetAttribute(fused_kernel,
                         cudaFuncAttributeMaxDynamicSharedMemorySize, SMEM_TOTAL);
    fused_kernel<<<dim3(16, 8), NTHR, SMEM_TOTAL>>>(fs, ft, out);
}

// round 10
// speedup vs baseline: 1.1629x; 1.0201x over previous
#include <cuda_runtime.h>
#include <cuda_bf16.h>
#include <cstdint>

#define BATCH 512
#define FEAT  512
#define NBLK  128
#define NTHR  512

#define AS_STR 520                         // 512 + 8 bf16 pad
#define AS_BYTES (64 * AS_STR * 2)         // 66560
#define BS_BYTES (32 * AS_STR * 2)         // 33280
#define SMEM_TOTAL (AS_BYTES + BS_BYTES)   // 99840

__device__ float g_S0[BATCH * BATCH];      // k in [0,256) partial S
__device__ float g_S1[BATCH * BATCH];      // k in [256,512) partial S
__device__ unsigned g_band[8];             // per-band arrival counters (monotonic)
__device__ unsigned long long g_sum = 0;
__device__ unsigned g_done = 0;

#define SUM_SCALE 1073741824.0f            // 2^30
#define INV_SUM   (1.0 / 1073741824.0)

__global__ void __launch_bounds__(NTHR, 1) fused_kernel(const float* __restrict__ fs,
                                                        const float* __restrict__ ft,
                                                        float* __restrict__ out) {
    extern __shared__ __align__(16) char smem[];
    __nv_bfloat16 (*As)[AS_STR] = (__nv_bfloat16(*)[AS_STR])smem;
    __nv_bfloat16 (*Bs)[AS_STR] = (__nv_bfloat16(*)[AS_STR])(smem + AS_BYTES);

    __shared__ float refs[4][8];
    __shared__ float wr[16][8];
    __shared__ unsigned band_base;

    const int tid   = threadIdx.x;
    const int bx    = blockIdx.x;          // 0..15 (nTile)
    const int by    = blockIdx.y;          // 0..7  (mTile band)
    const int bid   = by * 16 + bx;
    const int mTile = by * 64;
    const int nTile = bx * 32;
    const int warp  = tid >> 5;
    const int lane  = tid & 31;
    const int kh    = warp >> 3;           // k-half: 0 or 1
    const int wq    = warp & 7;
    const int wm    = wq & 3;
    const int wn    = wq >> 2;

    // entry snapshot of this band's counter (stream-serialized => quiescent)
    if (tid == 0) band_base = g_band[by];

    // ================= Stage A and B tiles (fp32 -> bf16) ====================
    {
        const float4* ag = (const float4*)(fs + mTile * FEAT);
        #pragma unroll 16
        for (int v = 0; v < 16; v++) {
            const int idx = tid + v * NTHR;
            const int row = idx >> 7, c4 = idx & 127;
            const float4 x = ag[row * 128 + c4];
            __nv_bfloat162 h0 = __floats2bfloat162_rn(x.x, x.y);
            __nv_bfloat162 h1 = __floats2bfloat162_rn(x.z, x.w);
            uint2 pk = make_uint2(*(uint32_t*)&h0, *(uint32_t*)&h1);
            *(uint2*)&As[row][c4 * 4] = pk;
        }
        const float4* bg = (const float4*)(ft + nTile * FEAT);
        #pragma unroll 8
        for (int v = 0; v < 8; v++) {
            const int idx = tid + v * NTHR;
            const int row = idx >> 7, c4 = idx & 127;
            const float4 x = bg[row * 128 + c4];
            __nv_bfloat162 h0 = __floats2bfloat162_rn(x.x, x.y);
            __nv_bfloat162 h1 = __floats2bfloat162_rn(x.z, x.w);
            uint2 pk = make_uint2(*(uint32_t*)&h0, *(uint32_t*)&h1);
            *(uint2*)&Bs[row][c4 * 4] = pk;
        }
    }
    __syncthreads();

    // ================= Mainloop: 16 k-steps per warp (k-half split) ==========
    float acc[2][4] = {};
    const int a_row = 16 * wm + (lane & 7) + ((lane >> 3) & 1) * 8;
    const int a_k8  = (lane >> 4) * 8;
    const int b_row = 16 * wn + (lane & 7) + (lane >> 4) * 8;
    const int b_k8  = ((lane >> 3) & 1) * 8;

    const uint32_t abase = (uint32_t)__cvta_generic_to_shared(&As[a_row][a_k8]) + kh * 512;
    const uint32_t bbase = (uint32_t)__cvta_generic_to_shared(&Bs[b_row][b_k8]) + kh * 512;

    #pragma unroll
    for (int kk = 0; kk < 16; kk++) {
        const uint32_t koff = kk * 32;     // bytes
        uint32_t a0, a1, a2, a3, b0, b1, b2, b3;
        asm volatile("ldmatrix.sync.aligned.m8n8.x4.shared.b16 {%0,%1,%2,%3}, [%4];\n"
                     : "=r"(a0), "=r"(a1), "=r"(a2), "=r"(a3) : "r"(abase + koff));
        asm volatile("ldmatrix.sync.aligned.m8n8.x4.shared.b16 {%0,%1,%2,%3}, [%4];\n"
                     : "=r"(b0), "=r"(b1), "=r"(b2), "=r"(b3) : "r"(bbase + koff));
        asm volatile("mma.sync.aligned.m16n8k16.row.col.f32.bf16.bf16.f32 "
                     "{%0,%1,%2,%3}, {%4,%5,%6,%7}, {%8,%9}, {%0,%1,%2,%3};\n"
                     : "+f"(acc[0][0]), "+f"(acc[0][1]), "+f"(acc[0][2]), "+f"(acc[0][3])
                     : "r"(a0), "r"(a1), "r"(a2), "r"(a3), "r"(b0), "r"(b1));
        asm volatile("mma.sync.aligned.m16n8k16.row.col.f32.bf16.bf16.f32 "
                     "{%0,%1,%2,%3}, {%4,%5,%6,%7}, {%8,%9}, {%0,%1,%2,%3};\n"
                     : "+f"(acc[1][0]), "+f"(acc[1][1]), "+f"(acc[1][2]), "+f"(acc[1][3])
                     : "r"(a0), "r"(a1), "r"(a2), "r"(a3), "r"(b2), "r"(b3));
    }

    // ================= Epilogue: each k-half STGs its partial S ==============
    {
        const int g = lane >> 2, t = lane & 3;
        const int row0 = mTile + 16 * wm + g;
        float* dst = kh ? g_S1 : g_S0;
        #pragma unroll
        for (int h = 0; h < 2; h++) {
            const int col = nTile + 16 * wn + t * 2 + 8 * h;
            *(float2*)&dst[row0 * BATCH + col]       = make_float2(acc[h][0], acc[h][1]);
            *(float2*)&dst[(row0 + 8) * BATCH + col] = make_float2(acc[h][2], acc[h][3]);
        }
    }
    __syncthreads();

    // ================= Band-local barrier (16 CTAs of band y) ================
    if (tid == 0) {
        __threadfence();
        atomicAdd(&g_band[by], 1u);
        const unsigned target = band_base + 16u;
        while ((int)(*(volatile unsigned*)&g_band[by] - target) < 0) {}
        __threadfence();
    }
    __syncthreads();

    // ================= Phase 2: rows y*64 + x*4 .. +3, 128 thr/row ===========
    const int row_l = tid >> 7;            // 0..3
    const int c     = tid & 127;           // float4 chunk
    const int r     = by * 64 + bx * 4 + row_l;
    const float4 u0 = ((const float4*)(g_S0 + r * BATCH))[c];
    const float4 u1 = ((const float4*)(g_S1 + r * BATCH))[c];
    const float4 v  = make_float4(u0.x + u1.x, u0.y + u1.y, u0.z + u1.z, u0.w + u1.w);

    const int rc0 = (r & ~7) >> 2;
    if (c == rc0)     *(float4*)&refs[row_l][0] = v;
    if (c == rc0 + 1) *(float4*)&refs[row_l][4] = v;
    __syncthreads();

    float p[8];
    #pragma unroll
    for (int j = 0; j < 8; j++) p[j] = refs[row_l][j];

    float s8[8];
    #pragma unroll
    for (int j = 0; j < 8; j++) {
        s8[j] = fmaxf(v.x - p[j], 0.f) + fmaxf(v.y - p[j], 0.f)
              + fmaxf(v.z - p[j], 0.f) + fmaxf(v.w - p[j], 0.f);
    }
    #pragma unroll
    for (int o = 16; o > 0; o >>= 1)
        #pragma unroll
        for (int j = 0; j < 8; j++)
            s8[j] += __shfl_down_sync(0xffffffffu, s8[j], o);
    if (lane == 0) {
        #pragma unroll
        for (int j = 0; j < 8; j++) wr[warp][j] = s8[j];
    }
    __syncthreads();

    float ratio = 0.f;
    if (tid < 32) {
        const int rl = tid >> 3, j = tid & 7;
        const float rk = 1.f + wr[rl * 4][j] + wr[rl * 4 + 1][j]
                             + wr[rl * 4 + 2][j] + wr[rl * 4 + 3][j];
        const float pj = refs[rl][j];
        float ps = 0.f;
        #pragma unroll
        for (int k = 0; k < 8; k++) ps += fmaxf(refs[rl][k] - pj, 0.f);
        ratio = (1.f + ps) / rk;
        #pragma unroll
        for (int o = 16; o > 0; o >>= 1)
            ratio += __shfl_down_sync(0xffffffffu, ratio, o);
    }

    // ================= Deterministic fixed-point tail ========================
    if (tid == 0) {
        atomicAdd(&g_sum, (unsigned long long)llrintf(ratio * SUM_SCALE));
        __threadfence();
        const unsigned prev = atomicAdd(&g_done, 1);
        if (prev == NBLK - 1) {
            const unsigned long long tot = *((volatile unsigned long long*)&g_sum);
            out[0] = (float)(1.0 - ((double)tot * INV_SUM) * (1.0 / 4096.0));
            g_sum  = 0;
            g_done = 0;
        }
    }
}

extern "C" void kernel_launch(void* const* d_in, const int* in_sizes, int n_in,
                              void* d_out, int out_size) {
    const float* fs = (const float*)d_in[0];
    const float* ft = (const float*)d_in[1];
    float* out = (float*)d_out;

    cudaFuncSetAttribute(fused_kernel,
                         cudaFuncAttributeMaxDynamicSharedMemorySize, SMEM_TOTAL);
    fused_kernel<<<dim3(16, 8), NTHR, SMEM_TOTAL>>>(fs, ft, out);
}